// round 7
// baseline (speedup 1.0000x reference)
#include <cuda_runtime.h>
#include <math.h>

// Problem dims
#define Bb   64
#define Ss   512
#define Tt   64
#define Hh   512
#define Dd   512
#define G3   1536          // 3*H
#define HB   (Hh*Bb)       // 32768, one hidden state in [j][b] layout

typedef unsigned long long ull;

// ---------------------------------------------------------------------------
// Scratch (device globals; no allocations allowed)
// ---------------------------------------------------------------------------
__device__ __align__(16) float g_gi[2][(size_t)Bb*Ss*G3];   // pre/post gate inputs [b][s][g]
__device__ __align__(16) float g_gid[(size_t)Bb*Tt*G3];     // decoder gate inputs  [b][t][g]
__device__ __align__(16) float g_hist[2][(size_t)(Ss+1)*HB];// encoder h history [t][j][b]
__device__ __align__(16) float g_dhist[(size_t)(Tt+1)*HB];  // decoder h history [t][j][b]
__device__ __align__(16) float g_score[Bb*2*Ss];            // score_enc [b][s2]
__device__ __align__(16) float g_hsc[Tt*Bb];                // decoder hidden scores [t][b]
__device__ int   g_dtok[Bb*Tt];                             // decoder input tokens
__device__ volatile unsigned g_arr[4];                      // grid-barrier arrive counters

// ---------------------------------------------------------------------------
// f32x2 packed-FMA helpers (FFMA2: 2 fp32 FMAs per issue; PTX-only on sm_10x)
// ---------------------------------------------------------------------------
__device__ __forceinline__ ull dup2(float x) {
    ull r; asm("mov.b64 %0, {%1, %1};" : "=l"(r) : "f"(x)); return r;
}
__device__ __forceinline__ void fma2(ull& d, ull a, ull b) {
    asm("fma.rn.f32x2 %0, %1, %2, %0;" : "+l"(d) : "l"(a), "l"(b));
}
__device__ __forceinline__ float2 upk(ull v) {
    float2 f; asm("mov.b64 {%0, %1}, %2;" : "=f"(f.x), "=f"(f.y) : "l"(v)); return f;
}
__device__ __forceinline__ float fsigmoid(float x) {
    return 1.f / (1.f + __expf(-x));
}

// ---------------------------------------------------------------------------
// init: zero h0 for both encoder GRUs + barrier counters
// ---------------------------------------------------------------------------
__global__ void init_kernel() {
    int i = blockIdx.x * blockDim.x + threadIdx.x;   // grid covers HB
    if (i < HB) { g_hist[0][i] = 0.f; g_hist[1][i] = 0.f; }
    if (i < 4) g_arr[i] = 0u;
}

// ---------------------------------------------------------------------------
// decoder tokens: [pre_seq[:, -1:], trg[:, :-1]]
// ---------------------------------------------------------------------------
__global__ void dectok_kernel(const int* __restrict__ pre_seq,
                              const int* __restrict__ trg) {
    int idx = blockIdx.x * blockDim.x + threadIdx.x;   // 0..4095
    if (idx >= Bb * Tt) return;
    int b = idx >> 6, t = idx & 63;
    g_dtok[idx] = (t == 0) ? pre_seq[b * Ss + (Ss - 1)] : trg[b * Tt + t - 1];
}

// ---------------------------------------------------------------------------
// Fused gather-GEMM:  C[m][n] = sum_k emb[token[m]][k] * W[n][k] + bias[n]
// Tiles: 128x128x16, 256 threads, 8x8 microtile, f32x2 inner product,
// register-prefetch software pipeline (next K-tile LDG issued before compute).
// dst: 0=gi_pre 1=gi_post 2=gi_dec
// ---------------------------------------------------------------------------
#define BK 16
__global__ __launch_bounds__(256, 2) void gemm_gather(
    const int* __restrict__ tokens_arg, int dst,
    const float* __restrict__ emb,
    const float* __restrict__ W,
    const float* __restrict__ bias)
{
    const int* tokens = (dst == 2) ? g_dtok : tokens_arg;
    float* C = (dst == 0) ? g_gi[0] : (dst == 1) ? g_gi[1] : g_gid;

    __shared__ __align__(16) float As[BK][128];
    __shared__ __align__(16) float Bs[BK][128];

    int tid = threadIdx.x;
    int m0 = blockIdx.x * 128;
    int n0 = blockIdx.y * 128;

    // staging: 128 rows x 16 k per tile; thread loads 2x float4
    int lrow = tid >> 1;            // 0..127
    int lcol = (tid & 1) << 2;      // 0 or 4

    int tok = tokens[m0 + lrow];
    const float* arow = emb + (size_t)tok * Dd + lcol;
    const float* brow = W + (size_t)(n0 + lrow) * Dd + lcol;

    int tx = tid & 15;              // n microtile (8 cols)
    int ty = tid >> 4;              // m microtile (8 rows)

    ull accp[8][4];
    #pragma unroll
    for (int i = 0; i < 8; i++)
        #pragma unroll
        for (int c = 0; c < 4; c++) accp[i][c] = 0ull;

    // prefetch first tile
    float4 a0 = *(const float4*)(arow);
    float4 a1 = *(const float4*)(arow + 8);
    float4 b0 = *(const float4*)(brow);
    float4 b1 = *(const float4*)(brow + 8);

    for (int k0 = 0; k0 < Dd; k0 += BK) {
        __syncthreads();
        As[lcol + 0][lrow] = a0.x; As[lcol + 1][lrow] = a0.y;
        As[lcol + 2][lrow] = a0.z; As[lcol + 3][lrow] = a0.w;
        As[lcol + 8][lrow] = a1.x; As[lcol + 9][lrow] = a1.y;
        As[lcol +10][lrow] = a1.z; As[lcol +11][lrow] = a1.w;
        Bs[lcol + 0][lrow] = b0.x; Bs[lcol + 1][lrow] = b0.y;
        Bs[lcol + 2][lrow] = b0.z; Bs[lcol + 3][lrow] = b0.w;
        Bs[lcol + 8][lrow] = b1.x; Bs[lcol + 9][lrow] = b1.y;
        Bs[lcol +10][lrow] = b1.z; Bs[lcol +11][lrow] = b1.w;
        __syncthreads();
        if (k0 + BK < Dd) {     // prefetch next tile; overlaps compute below
            a0 = *(const float4*)(arow + k0 + BK);
            a1 = *(const float4*)(arow + k0 + BK + 8);
            b0 = *(const float4*)(brow + k0 + BK);
            b1 = *(const float4*)(brow + k0 + BK + 8);
        }
        #pragma unroll
        for (int kk = 0; kk < BK; kk++) {
            float4 av0 = *(const float4*)&As[kk][ty * 8];
            float4 av1 = *(const float4*)&As[kk][ty * 8 + 4];
            ulonglong2 bv0 = *(const ulonglong2*)&Bs[kk][tx * 8];
            ulonglong2 bv1 = *(const ulonglong2*)&Bs[kk][tx * 8 + 4];
            ull ad[8];
            ad[0] = dup2(av0.x); ad[1] = dup2(av0.y);
            ad[2] = dup2(av0.z); ad[3] = dup2(av0.w);
            ad[4] = dup2(av1.x); ad[5] = dup2(av1.y);
            ad[6] = dup2(av1.z); ad[7] = dup2(av1.w);
            #pragma unroll
            for (int i = 0; i < 8; i++) {
                fma2(accp[i][0], ad[i], bv0.x);
                fma2(accp[i][1], ad[i], bv0.y);
                fma2(accp[i][2], ad[i], bv1.x);
                fma2(accp[i][3], ad[i], bv1.y);
            }
        }
    }

    int n = n0 + tx * 8;
    float4 bo0 = *(const float4*)(bias + n);
    float4 bo1 = *(const float4*)(bias + n + 4);
    #pragma unroll
    for (int i = 0; i < 8; i++) {
        int m = m0 + ty * 8 + i;
        float2 c0 = upk(accp[i][0]), c1 = upk(accp[i][1]);
        float2 c2 = upk(accp[i][2]), c3 = upk(accp[i][3]);
        float4 o0, o1;
        o0.x = c0.x + bo0.x; o0.y = c0.y + bo0.y;
        o0.z = c1.x + bo0.z; o0.w = c1.y + bo0.w;
        o1.x = c2.x + bo1.x; o1.y = c2.y + bo1.y;
        o1.z = c3.x + bo1.z; o1.w = c3.y + bo1.w;
        __stcs((float4*)&C[(size_t)m * G3 + n],     o0);
        __stcs((float4*)&C[(size_t)m * G3 + n + 4], o1);
    }
}

// ---------------------------------------------------------------------------
// Persistent GRU recurrence. One launch runs ALL timesteps.
// Grid (64, nGru). Each CTA owns 8 h-columns of one GRU; its Whh slice lives
// in 96KB dynamic smem (each value duplicated -> direct f32x2 operands).
// h reads are PLAIN LDG (L1-cached; 8 warps dedupe in L1 -> 16MB/step from L2
// instead of 128MB with __ldcg). Coherent because hist[t+1] addresses are
// never read before written and STG is write-through to L2.
// Per-step sync: release fence + atomic arrive + spin (nanosleep backoff).
// Residency: <=128 CTAs, 96KB smem -> one wave, no deadlock.
// ---------------------------------------------------------------------------
__global__ __launch_bounds__(256) void gru_persist(
    int isDec,
    const float* __restrict__ Whh0, const float* __restrict__ Whh1,
    const float* __restrict__ bhh0, const float* __restrict__ bhh1)
{
    extern __shared__ __align__(16) float swd[];   // 24*512*2 floats = 96KB
    int gru = blockIdx.y;
    const float* gi  = isDec ? g_gid : g_gi[gru];
    float* hist      = isDec ? g_dhist : g_hist[gru];
    const float* Whh = gru ? Whh1 : Whh0;
    const float* bhh = gru ? bhh1 : bhh0;
    int seq = isDec ? Tt : Ss;
    int cid = isDec ? 2 : gru;

    int tid = threadIdx.x;
    int j0 = blockIdx.x * 8;

    // Stage Whh slice once, duplicated: swd[2*idx] = swd[2*idx+1] = w
    for (int idx = tid; idx < 24 * 512; idx += 256) {
        int r = idx >> 9, k = idx & 511;
        int gate = r >> 3, jj = r & 7;
        float w = Whh[(size_t)(gate * Hh + j0 + jj) * Hh + k];
        swd[idx * 2] = w; swd[idx * 2 + 1] = w;
    }
    __syncthreads();

    int jj = tid >> 5;    // 0..7  (warp id -> uniform smem reads = broadcast)
    int bg = tid & 31;    // 0..31 -> batch pair (2*bg, 2*bg+1)
    int j = j0 + jj;
    float br = bhh[j], bz = bhh[Hh + j], bn = bhh[2 * Hh + j];
    const ulonglong2* wr2 = (const ulonglong2*)(swd + jj * 1024);
    const ulonglong2* wz2 = (const ulonglong2*)(swd + (8 + jj) * 1024);
    const ulonglong2* wn2 = (const ulonglong2*)(swd + (16 + jj) * 1024);

    for (int t = 0; t < seq; t++) {
        const ull* h8 = (const ull*)(hist + (size_t)t * HB);
        ull accr = 0ull, accz = 0ull, accn = 0ull;
        const ull* hp = h8 + bg;
        #pragma unroll 8
        for (int k2 = 0; k2 < 256; k2++) {      // 2 k-values per iter
            ulonglong2 wr = wr2[k2], wz = wz2[k2], wn = wn2[k2];
            ull hA = hp[0];                     // k = 2*k2   (plain LDG, L1)
            ull hB = hp[32];                    // k = 2*k2+1
            hp += 64;
            fma2(accr, hA, wr.x); fma2(accz, hA, wz.x); fma2(accn, hA, wn.x);
            fma2(accr, hB, wr.y); fma2(accz, hB, wz.y); fma2(accn, hB, wn.y);
        }
        float2 ar = upk(accr), az = upk(accz), an = upk(accn);
        float2 hold = upk(h8[j * 32 + bg]);
        float accrv[2] = {ar.x, ar.y}, acczv[2] = {az.x, az.y};
        float accnv[2] = {an.x, an.y}, holdv[2] = {hold.x, hold.y};
        float ho[2];
        #pragma unroll
        for (int i = 0; i < 2; i++) {
            int b = bg * 2 + i;
            const float* g = gi + ((size_t)b * seq + t) * G3;
            float r = fsigmoid(g[j]      + accrv[i] + br);
            float z = fsigmoid(g[Hh + j] + acczv[i] + bz);
            float x = g[2 * Hh + j] + r * (accnv[i] + bn);
            float e = __expf(2.f * x);
            float nn = (e - 1.f) / (e + 1.f);   // tanh(x)
            ho[i] = (1.f - z) * nn + z * holdv[i];
        }
        *(float2*)&hist[(size_t)(t + 1) * HB + j * Bb + bg * 2] =
            make_float2(ho[0], ho[1]);

        // ---- grid barrier among the 64 CTAs of this GRU group ----
        __threadfence();           // release h_out stores to L2
        __syncthreads();           // whole CTA has released
        if (tid == 0) {
            atomicAdd((unsigned*)&g_arr[cid], 1u);
            unsigned target = (unsigned)(t + 1) * 64u;
            while (g_arr[cid] < target) __nanosleep(64);
        }
        __syncthreads();
    }
}

// ---------------------------------------------------------------------------
// score_enc[b][gru*S + t] = sum_j relu(h_{t+1}[j][b]) * w_enc[j]
// ---------------------------------------------------------------------------
__global__ __launch_bounds__(64) void score_kernel(const float* __restrict__ out_w) {
    int t = blockIdx.x, gru = blockIdx.y, b = threadIdx.x;
    const float* hrow = g_hist[gru] + (size_t)(t + 1) * HB;
    float acc = 0.f;
    for (int j = 0; j < Hh; j++)
        acc += fmaxf(hrow[j * Bb + b], 0.f) * out_w[j];
    g_score[b * (2 * Ss) + gru * Ss + t] = acc;
}

// ---------------------------------------------------------------------------
// enc_hidden (decoder h0) = tanh(cat(pre_h, post_h) @ enc_fc_w^T + enc_fc_b)
// ---------------------------------------------------------------------------
__global__ __launch_bounds__(64) void ench_kernel(const float* __restrict__ enc_fc_w,
                                                  const float* __restrict__ enc_fc_b) {
    int i = blockIdx.x, b = threadIdx.x;
    const float* w = enc_fc_w + (size_t)i * (2 * Hh);
    const float* hp0 = g_hist[0] + (size_t)Ss * HB;
    const float* hp1 = g_hist[1] + (size_t)Ss * HB;
    float acc = enc_fc_b[i];
    for (int q = 0; q < Hh; q++) acc += hp0[q * Bb + b] * w[q];
    for (int q = 0; q < Hh; q++) acc += hp1[q * Bb + b] * w[Hh + q];
    g_dhist[i * Bb + b] = tanhf(acc);
}

// ---------------------------------------------------------------------------
// decoder hidden score: hsc[t][b] = relu(hdec_{t+1}[:,b]) . w_hid + out_b
// ---------------------------------------------------------------------------
__global__ __launch_bounds__(64) void hsc_kernel(const float* __restrict__ out_w,
                                                 const float* __restrict__ out_b) {
    int t = blockIdx.x, b = threadIdx.x;
    const float* hrow = g_dhist + (size_t)(t + 1) * HB;
    float acc = 0.f;
    for (int j = 0; j < Hh; j++)
        acc += fmaxf(hrow[j * Bb + b], 0.f) * out_w[Hh + j];
    g_hsc[t * Bb + b] = acc + out_b[0];
}

// ---------------------------------------------------------------------------
// probs: out_pre[b][t][s] = sigmoid(score[b][s] + hsc[t][b]); post analogous
// ---------------------------------------------------------------------------
__global__ __launch_bounds__(256) void probs_kernel(float* __restrict__ out) {
    int bt = blockIdx.x;             // 0..4095
    int b = bt >> 6, t = bt & 63;
    float hs = g_hsc[t * Bb + b];
    const float* sc = g_score + b * (2 * Ss);
    float* out_pre  = out + (size_t)bt * Ss;
    float* out_post = out + (size_t)Bb * Tt * Ss + (size_t)bt * Ss;
    #pragma unroll
    for (int it = 0; it < 4; it++) {
        int s2 = it * 256 + threadIdx.x;
        float l = sc[s2] + hs;
        float p = 1.f / (1.f + expf(-l));
        if (s2 < Ss) out_pre[s2] = p;
        else         out_post[s2 - Ss] = p;
    }
}

// ---------------------------------------------------------------------------
// launch
// ---------------------------------------------------------------------------
extern "C" void kernel_launch(void* const* d_in, const int* in_sizes, int n_in,
                              void* d_out, int out_size) {
    const int*   pre_seq   = (const int*)  d_in[0];
    const int*   post_seq  = (const int*)  d_in[1];
    const int*   trg       = (const int*)  d_in[2];
    const float* emb       = (const float*)d_in[3];
    const float* pre_Wih   = (const float*)d_in[4];
    const float* pre_Whh   = (const float*)d_in[5];
    const float* pre_bih   = (const float*)d_in[6];
    const float* pre_bhh   = (const float*)d_in[7];
    const float* post_Wih  = (const float*)d_in[8];
    const float* post_Whh  = (const float*)d_in[9];
    const float* post_bih  = (const float*)d_in[10];
    const float* post_bhh  = (const float*)d_in[11];
    const float* enc_fc_w  = (const float*)d_in[12];
    const float* enc_fc_b  = (const float*)d_in[13];
    const float* dec_Wih   = (const float*)d_in[14];
    const float* dec_Whh   = (const float*)d_in[15];
    const float* dec_bih   = (const float*)d_in[16];
    const float* dec_bhh   = (const float*)d_in[17];
    const float* out_w     = (const float*)d_in[18];
    const float* out_b     = (const float*)d_in[19];
    float* out = (float*)d_out;

    const int SMEM_GRU = 24 * 512 * 2 * 4;   // 96KB dynamic
    cudaFuncSetAttribute(gru_persist,
                         cudaFuncAttributeMaxDynamicSharedMemorySize, SMEM_GRU);

    // h0 = 0, barrier counters = 0, decoder token assembly
    init_kernel<<<128, 256>>>();
    dectok_kernel<<<16, 256>>>(pre_seq, trg);

    // Gate-input GEMMs (fused embedding gather): gi = emb[tok] @ Wih^T + bih
    gemm_gather<<<dim3(Bb * Ss / 128, G3 / 128), 256>>>(pre_seq,  0, emb, pre_Wih,  pre_bih);
    gemm_gather<<<dim3(Bb * Ss / 128, G3 / 128), 256>>>(post_seq, 1, emb, post_Wih, post_bih);
    gemm_gather<<<dim3(Bb * Tt / 128, G3 / 128), 256>>>(nullptr,  2, emb, dec_Wih,  dec_bih);

    // Encoder recurrences: single persistent launch, both GRUs (128 CTAs)
    gru_persist<<<dim3(64, 2), 256, SMEM_GRU>>>(0, pre_Whh, post_Whh, pre_bhh, post_bhh);

    // score_enc over all encoder outputs; decoder initial hidden
    score_kernel<<<dim3(Ss, 2), 64>>>(out_w);
    ench_kernel<<<Hh, 64>>>(enc_fc_w, enc_fc_b);

    // Decoder recurrence: persistent (64 CTAs)
    gru_persist<<<dim3(64, 1), 256, SMEM_GRU>>>(1, dec_Whh, dec_Whh, dec_bhh, dec_bhh);

    // Logits -> probabilities -> output
    hsc_kernel<<<Tt, 64>>>(out_w, out_b);
    probs_kernel<<<Bb * Tt, 256>>>(out);
}

// round 8
// speedup vs baseline: 1.1368x; 1.1368x over previous
#include <cuda_runtime.h>
#include <math.h>

// Problem dims
#define Bb   64
#define Ss   512
#define Tt   64
#define Hh   512
#define Dd   512
#define G3   1536          // 3*H
#define HB   (Hh*Bb)       // 32768, one hidden state in [j][b] layout

typedef unsigned long long ull;

// ---------------------------------------------------------------------------
// Scratch (device globals; no allocations allowed)
// ---------------------------------------------------------------------------
__device__ __align__(16) float g_gi[2][(size_t)Bb*Ss*G3];   // pre/post gate inputs [b][s][g]
__device__ __align__(16) float g_gid[(size_t)Bb*Tt*G3];     // decoder gate inputs  [b][t][g]
__device__ __align__(16) float g_hist[2][(size_t)(Ss+1)*HB];// encoder h history [t][j][b]
__device__ __align__(16) float g_dhist[(size_t)(Tt+1)*HB];  // decoder h history [t][j][b]
__device__ __align__(16) float g_score[Bb*2*Ss];            // score_enc [b][s2]
__device__ __align__(16) float g_hsc[Tt*Bb];                // decoder hidden scores [t][b]
__device__ int   g_dtok[Bb*Tt];                             // decoder input tokens

// ---------------------------------------------------------------------------
// f32x2 packed-FMA helpers (FFMA2: 2 fp32 FMAs per issue; PTX-only on sm_10x)
// ---------------------------------------------------------------------------
__device__ __forceinline__ ull dup2(float x) {
    ull r; asm("mov.b64 %0, {%1, %1};" : "=l"(r) : "f"(x)); return r;
}
__device__ __forceinline__ void fma2(ull& d, ull a, ull b) {
    asm("fma.rn.f32x2 %0, %1, %2, %0;" : "+l"(d) : "l"(a), "l"(b));
}
__device__ __forceinline__ float2 upk(ull v) {
    float2 f; asm("mov.b64 {%0, %1}, %2;" : "=f"(f.x), "=f"(f.y) : "l"(v)); return f;
}
__device__ __forceinline__ float fsigmoid(float x) {
    return 1.f / (1.f + __expf(-x));
}

// ---------------------------------------------------------------------------
// init: zero h0 for both encoder GRUs
// ---------------------------------------------------------------------------
__global__ void init_kernel() {
    int i = blockIdx.x * blockDim.x + threadIdx.x;   // grid covers HB
    if (i < HB) { g_hist[0][i] = 0.f; g_hist[1][i] = 0.f; }
}

// ---------------------------------------------------------------------------
// decoder tokens: [pre_seq[:, -1:], trg[:, :-1]]
// ---------------------------------------------------------------------------
__global__ void dectok_kernel(const int* __restrict__ pre_seq,
                              const int* __restrict__ trg) {
    int idx = blockIdx.x * blockDim.x + threadIdx.x;   // 0..4095
    if (idx >= Bb * Tt) return;
    int b = idx >> 6, t = idx & 63;
    g_dtok[idx] = (t == 0) ? pre_seq[b * Ss + (Ss - 1)] : trg[b * Tt + t - 1];
}

// ---------------------------------------------------------------------------
// Fused gather-GEMM:  C[m][n] = sum_k emb[token[m]][k] * W[n][k] + bias[n]
// Tiles: 128x128x16, 256 threads, 8x8 microtile, f32x2 inner product,
// register-prefetch software pipeline. dst: 0=gi_pre 1=gi_post 2=gi_dec
// ---------------------------------------------------------------------------
#define BK 16
__global__ __launch_bounds__(256, 2) void gemm_gather(
    const int* __restrict__ tokens_arg, int dst,
    const float* __restrict__ emb,
    const float* __restrict__ W,
    const float* __restrict__ bias)
{
    const int* tokens = (dst == 2) ? g_dtok : tokens_arg;
    float* C = (dst == 0) ? g_gi[0] : (dst == 1) ? g_gi[1] : g_gid;

    __shared__ __align__(16) float As[BK][128];
    __shared__ __align__(16) float Bs[BK][128];

    int tid = threadIdx.x;
    int m0 = blockIdx.x * 128;
    int n0 = blockIdx.y * 128;

    // staging: 128 rows x 16 k per tile; thread loads 2x float4
    int lrow = tid >> 1;            // 0..127
    int lcol = (tid & 1) << 2;      // 0 or 4

    int tok = tokens[m0 + lrow];
    const float* arow = emb + (size_t)tok * Dd + lcol;
    const float* brow = W + (size_t)(n0 + lrow) * Dd + lcol;

    int tx = tid & 15;              // n microtile (8 cols)
    int ty = tid >> 4;              // m microtile (8 rows)

    ull accp[8][4];
    #pragma unroll
    for (int i = 0; i < 8; i++)
        #pragma unroll
        for (int c = 0; c < 4; c++) accp[i][c] = 0ull;

    // prefetch first tile
    float4 a0 = *(const float4*)(arow);
    float4 a1 = *(const float4*)(arow + 8);
    float4 b0 = *(const float4*)(brow);
    float4 b1 = *(const float4*)(brow + 8);

    for (int k0 = 0; k0 < Dd; k0 += BK) {
        __syncthreads();
        As[lcol + 0][lrow] = a0.x; As[lcol + 1][lrow] = a0.y;
        As[lcol + 2][lrow] = a0.z; As[lcol + 3][lrow] = a0.w;
        As[lcol + 8][lrow] = a1.x; As[lcol + 9][lrow] = a1.y;
        As[lcol +10][lrow] = a1.z; As[lcol +11][lrow] = a1.w;
        Bs[lcol + 0][lrow] = b0.x; Bs[lcol + 1][lrow] = b0.y;
        Bs[lcol + 2][lrow] = b0.z; Bs[lcol + 3][lrow] = b0.w;
        Bs[lcol + 8][lrow] = b1.x; Bs[lcol + 9][lrow] = b1.y;
        Bs[lcol +10][lrow] = b1.z; Bs[lcol +11][lrow] = b1.w;
        __syncthreads();
        if (k0 + BK < Dd) {     // prefetch next tile; overlaps compute below
            a0 = *(const float4*)(arow + k0 + BK);
            a1 = *(const float4*)(arow + k0 + BK + 8);
            b0 = *(const float4*)(brow + k0 + BK);
            b1 = *(const float4*)(brow + k0 + BK + 8);
        }
        #pragma unroll
        for (int kk = 0; kk < BK; kk++) {
            float4 av0 = *(const float4*)&As[kk][ty * 8];
            float4 av1 = *(const float4*)&As[kk][ty * 8 + 4];
            ulonglong2 bv0 = *(const ulonglong2*)&Bs[kk][tx * 8];
            ulonglong2 bv1 = *(const ulonglong2*)&Bs[kk][tx * 8 + 4];
            ull ad[8];
            ad[0] = dup2(av0.x); ad[1] = dup2(av0.y);
            ad[2] = dup2(av0.z); ad[3] = dup2(av0.w);
            ad[4] = dup2(av1.x); ad[5] = dup2(av1.y);
            ad[6] = dup2(av1.z); ad[7] = dup2(av1.w);
            #pragma unroll
            for (int i = 0; i < 8; i++) {
                fma2(accp[i][0], ad[i], bv0.x);
                fma2(accp[i][1], ad[i], bv0.y);
                fma2(accp[i][2], ad[i], bv1.x);
                fma2(accp[i][3], ad[i], bv1.y);
            }
        }
    }

    int n = n0 + tx * 8;
    float4 bo0 = *(const float4*)(bias + n);
    float4 bo1 = *(const float4*)(bias + n + 4);
    #pragma unroll
    for (int i = 0; i < 8; i++) {
        int m = m0 + ty * 8 + i;
        float2 c0 = upk(accp[i][0]), c1 = upk(accp[i][1]);
        float2 c2 = upk(accp[i][2]), c3 = upk(accp[i][3]);
        float4 o0, o1;
        o0.x = c0.x + bo0.x; o0.y = c0.y + bo0.y;
        o0.z = c1.x + bo0.z; o0.w = c1.y + bo0.w;
        o1.x = c2.x + bo1.x; o1.y = c2.y + bo1.y;
        o1.z = c3.x + bo1.z; o1.w = c3.y + bo1.w;
        __stcs((float4*)&C[(size_t)m * G3 + n],     o0);
        __stcs((float4*)&C[(size_t)m * G3 + n + 4], o1);
    }
}

// ---------------------------------------------------------------------------
// GRU step (ONE timestep per launch; kernel boundary = free global barrier).
// Grid (64, nGru). CTA owns 8 h-columns; Whh slice duplicated into 96KB
// dynamic smem (direct f32x2 operands). 256 threads:
//   jj = tid>>5 (h-column within CTA; warp-uniform -> LDS broadcast)
//   bg = tid&31 (batch pair 2*bg, 2*bg+1; LDG.64 coalesced over [j][b] layout)
// Inner loop per 2 k-values: 3 LDS.128 + 2 LDG.64 + 6 fma.rn.f32x2.
// ---------------------------------------------------------------------------
__global__ __launch_bounds__(256) void gru_step(
    int isDec, int t,
    const float* __restrict__ Whh0, const float* __restrict__ Whh1,
    const float* __restrict__ bhh0, const float* __restrict__ bhh1)
{
    extern __shared__ __align__(16) float swd[];   // 24*512*2 floats = 96KB
    int gru = blockIdx.y;
    const float* gi  = isDec ? g_gid : g_gi[gru];
    float* hist      = isDec ? g_dhist : g_hist[gru];
    const float* Whh = gru ? Whh1 : Whh0;
    const float* bhh = gru ? bhh1 : bhh0;
    int seq = isDec ? Tt : Ss;

    int tid = threadIdx.x;
    int j0 = blockIdx.x * 8;

    // Stage Whh slice duplicated: thread loads float4, writes 2 paired float4
    for (int i = tid; i < 3072; i += 256) {        // 3072 float4 = 12288 w
        int r = i >> 7;          // 0..23 (gate*8 + jj)
        int c = i & 127;         // float4 index within 512-wide row
        int gate = r >> 3, jj = r & 7;
        float4 w = *(const float4*)&Whh[(size_t)(gate * Hh + j0 + jj) * Hh + c * 4];
        float4* d = (float4*)&swd[r * 1024 + c * 8];
        d[0] = make_float4(w.x, w.x, w.y, w.y);
        d[1] = make_float4(w.z, w.z, w.w, w.w);
    }
    __syncthreads();

    int jj = tid >> 5;    // 0..7
    int bg = tid & 31;    // 0..31 -> batch pair
    int j = j0 + jj;
    float br = bhh[j], bz = bhh[Hh + j], bn = bhh[2 * Hh + j];
    const ulonglong2* wr2 = (const ulonglong2*)(swd + jj * 1024);
    const ulonglong2* wz2 = (const ulonglong2*)(swd + (8 + jj) * 1024);
    const ulonglong2* wn2 = (const ulonglong2*)(swd + (16 + jj) * 1024);

    const ull* h8 = (const ull*)(hist + (size_t)t * HB);
    ull accr = 0ull, accz = 0ull, accn = 0ull;
    const ull* hp = h8 + bg;
    #pragma unroll 8
    for (int k2 = 0; k2 < 256; k2++) {      // 2 k-values per iter
        ulonglong2 wr = wr2[k2], wz = wz2[k2], wn = wn2[k2];
        ull hA = hp[0];                     // k = 2*k2
        ull hB = hp[32];                    // k = 2*k2+1
        hp += 64;
        fma2(accr, hA, wr.x); fma2(accz, hA, wz.x); fma2(accn, hA, wn.x);
        fma2(accr, hB, wr.y); fma2(accz, hB, wz.y); fma2(accn, hB, wn.y);
    }
    float2 ar = upk(accr), az = upk(accz), an = upk(accn);
    float2 hold = upk(h8[j * 32 + bg]);
    float accrv[2] = {ar.x, ar.y}, acczv[2] = {az.x, az.y};
    float accnv[2] = {an.x, an.y}, holdv[2] = {hold.x, hold.y};
    float ho[2];
    #pragma unroll
    for (int i = 0; i < 2; i++) {
        int b = bg * 2 + i;
        const float* g = gi + ((size_t)b * seq + t) * G3;
        float r = fsigmoid(g[j]      + accrv[i] + br);
        float z = fsigmoid(g[Hh + j] + acczv[i] + bz);
        float x = g[2 * Hh + j] + r * (accnv[i] + bn);
        float e = __expf(2.f * x);
        float nn = (e - 1.f) / (e + 1.f);   // tanh(x)
        ho[i] = (1.f - z) * nn + z * holdv[i];
    }
    *(float2*)&hist[(size_t)(t + 1) * HB + j * Bb + bg * 2] =
        make_float2(ho[0], ho[1]);
}

// ---------------------------------------------------------------------------
// score_enc[b][gru*S + t] = sum_j relu(h_{t+1}[j][b]) * w_enc[j]
// ---------------------------------------------------------------------------
__global__ __launch_bounds__(64) void score_kernel(const float* __restrict__ out_w) {
    int t = blockIdx.x, gru = blockIdx.y, b = threadIdx.x;
    const float* hrow = g_hist[gru] + (size_t)(t + 1) * HB;
    float acc = 0.f;
    for (int j = 0; j < Hh; j++)
        acc += fmaxf(hrow[j * Bb + b], 0.f) * out_w[j];
    g_score[b * (2 * Ss) + gru * Ss + t] = acc;
}

// ---------------------------------------------------------------------------
// enc_hidden (decoder h0) = tanh(cat(pre_h, post_h) @ enc_fc_w^T + enc_fc_b)
// ---------------------------------------------------------------------------
__global__ __launch_bounds__(64) void ench_kernel(const float* __restrict__ enc_fc_w,
                                                  const float* __restrict__ enc_fc_b) {
    int i = blockIdx.x, b = threadIdx.x;
    const float* w = enc_fc_w + (size_t)i * (2 * Hh);
    const float* hp0 = g_hist[0] + (size_t)Ss * HB;
    const float* hp1 = g_hist[1] + (size_t)Ss * HB;
    float acc = enc_fc_b[i];
    for (int q = 0; q < Hh; q++) acc += hp0[q * Bb + b] * w[q];
    for (int q = 0; q < Hh; q++) acc += hp1[q * Bb + b] * w[Hh + q];
    g_dhist[i * Bb + b] = tanhf(acc);
}

// ---------------------------------------------------------------------------
// decoder hidden score: hsc[t][b] = relu(hdec_{t+1}[:,b]) . w_hid + out_b
// ---------------------------------------------------------------------------
__global__ __launch_bounds__(64) void hsc_kernel(const float* __restrict__ out_w,
                                                 const float* __restrict__ out_b) {
    int t = blockIdx.x, b = threadIdx.x;
    const float* hrow = g_dhist + (size_t)(t + 1) * HB;
    float acc = 0.f;
    for (int j = 0; j < Hh; j++)
        acc += fmaxf(hrow[j * Bb + b], 0.f) * out_w[Hh + j];
    g_hsc[t * Bb + b] = acc + out_b[0];
}

// ---------------------------------------------------------------------------
// probs: out_pre[b][t][s] = sigmoid(score[b][s] + hsc[t][b]); post analogous
// ---------------------------------------------------------------------------
__global__ __launch_bounds__(256) void probs_kernel(float* __restrict__ out) {
    int bt = blockIdx.x;             // 0..4095
    int b = bt >> 6, t = bt & 63;
    float hs = g_hsc[t * Bb + b];
    const float* sc = g_score + b * (2 * Ss);
    float* out_pre  = out + (size_t)bt * Ss;
    float* out_post = out + (size_t)Bb * Tt * Ss + (size_t)bt * Ss;
    #pragma unroll
    for (int it = 0; it < 4; it++) {
        int s2 = it * 256 + threadIdx.x;
        float l = sc[s2] + hs;
        float p = 1.f / (1.f + expf(-l));
        if (s2 < Ss) out_pre[s2] = p;
        else         out_post[s2 - Ss] = p;
    }
}

// ---------------------------------------------------------------------------
// launch
// ---------------------------------------------------------------------------
extern "C" void kernel_launch(void* const* d_in, const int* in_sizes, int n_in,
                              void* d_out, int out_size) {
    const int*   pre_seq   = (const int*)  d_in[0];
    const int*   post_seq  = (const int*)  d_in[1];
    const int*   trg       = (const int*)  d_in[2];
    const float* emb       = (const float*)d_in[3];
    const float* pre_Wih   = (const float*)d_in[4];
    const float* pre_Whh   = (const float*)d_in[5];
    const float* pre_bih   = (const float*)d_in[6];
    const float* pre_bhh   = (const float*)d_in[7];
    const float* post_Wih  = (const float*)d_in[8];
    const float* post_Whh  = (const float*)d_in[9];
    const float* post_bih  = (const float*)d_in[10];
    const float* post_bhh  = (const float*)d_in[11];
    const float* enc_fc_w  = (const float*)d_in[12];
    const float* enc_fc_b  = (const float*)d_in[13];
    const float* dec_Wih   = (const float*)d_in[14];
    const float* dec_Whh   = (const float*)d_in[15];
    const float* dec_bih   = (const float*)d_in[16];
    const float* dec_bhh   = (const float*)d_in[17];
    const float* out_w     = (const float*)d_in[18];
    const float* out_b     = (const float*)d_in[19];
    float* out = (float*)d_out;

    const int SMEM_GRU = 24 * 512 * 2 * 4;   // 96KB dynamic
    cudaFuncSetAttribute(gru_step,
                         cudaFuncAttributeMaxDynamicSharedMemorySize, SMEM_GRU);

    // h0 = 0, decoder token assembly
    init_kernel<<<128, 256>>>();
    dectok_kernel<<<16, 256>>>(pre_seq, trg);

    // Gate-input GEMMs (fused embedding gather): gi = emb[tok] @ Wih^T + bih
    gemm_gather<<<dim3(Bb * Ss / 128, G3 / 128), 256>>>(pre_seq,  0, emb, pre_Wih,  pre_bih);
    gemm_gather<<<dim3(Bb * Ss / 128, G3 / 128), 256>>>(post_seq, 1, emb, post_Wih, post_bih);
    gemm_gather<<<dim3(Bb * Tt / 128, G3 / 128), 256>>>(nullptr,  2, emb, dec_Wih,  dec_bih);

    // Encoder recurrences (pre + post in one grid per step)
    for (int t = 0; t < Ss; t++)
        gru_step<<<dim3(64, 2), 256, SMEM_GRU>>>(0, t, pre_Whh, post_Whh, pre_bhh, post_bhh);

    // score_enc over all encoder outputs; decoder initial hidden
    score_kernel<<<dim3(Ss, 2), 64>>>(out_w);
    ench_kernel<<<Hh, 64>>>(enc_fc_w, enc_fc_b);

    // Decoder recurrence
    for (int t = 0; t < Tt; t++)
        gru_step<<<dim3(64, 1), 256, SMEM_GRU>>>(1, t, dec_Whh, dec_Whh, dec_bhh, dec_bhh);

    // Logits -> probabilities -> output
    hsc_kernel<<<Tt, 64>>>(out_w, out_b);
    probs_kernel<<<Bb * Tt, 256>>>(out);
}

// round 9
// speedup vs baseline: 1.7821x; 1.5676x over previous
#include <cuda_runtime.h>
#include <cuda_bf16.h>
#include <math.h>

// Problem dims
#define Bb   64
#define Ss   512
#define Tt   64
#define Hh   512
#define Dd   512
#define G3   1536          // 3*H
#define HB   (Hh*Bb)       // 32768, one hidden state in [j][b] layout

// ---------------------------------------------------------------------------
// Scratch (device globals; no allocations allowed)
// ---------------------------------------------------------------------------
__device__ __align__(16) float g_gi[2][(size_t)Bb*Ss*G3];   // pre/post gate inputs [b][s][g]
__device__ __align__(16) float g_gid[(size_t)Bb*Tt*G3];     // decoder gate inputs  [b][t][g]
__device__ __align__(16) float g_hist[2][(size_t)(Ss+1)*HB];// encoder h history [t][j][b]
__device__ __align__(16) float g_dhist[(size_t)(Tt+1)*HB];  // decoder h history [t][j][b]
__device__ __align__(16) float g_score[Bb*2*Ss];            // score_enc [b][s2]
__device__ __align__(16) float g_hsc[Tt*Bb];                // decoder hidden scores [t][b]
__device__ int   g_dtok[Bb*Tt];                              // decoder input tokens

// ---------------------------------------------------------------------------
// init: zero h0 for both encoder GRUs
// ---------------------------------------------------------------------------
__global__ void init_kernel() {
    int i = blockIdx.x * blockDim.x + threadIdx.x;   // grid covers HB
    if (i < HB) { g_hist[0][i] = 0.f; g_hist[1][i] = 0.f; }
}

// ---------------------------------------------------------------------------
// decoder tokens: [pre_seq[:, -1:], trg[:, :-1]]
// ---------------------------------------------------------------------------
__global__ void dectok_kernel(const int* __restrict__ pre_seq,
                              const int* __restrict__ trg) {
    int idx = blockIdx.x * blockDim.x + threadIdx.x;   // 0..4095
    if (idx >= Bb * Tt) return;
    int b = idx >> 6, t = idx & 63;
    g_dtok[idx] = (t == 0) ? pre_seq[b * Ss + (Ss - 1)] : trg[b * Tt + t - 1];
}

// ---------------------------------------------------------------------------
// Fused gather-GEMM:  C[m][n] = sum_k emb[token[m]][k] * W[n][k] + bias[n]
// Tile 64(M)x128(N)x16(K), 256 threads, 8x4 microtile.
// Occupancy-first design: 32 acc regs -> ~70 total -> 3 CTAs/SM (6 warps/SMSP)
// so FMA pipe stays fed across LDS latency and __syncthreads.
// A-fragment LDS reads are warp-uniform (broadcast). Register prefetch of the
// next K-tile overlaps global loads with compute.
// dst: 0=gi_pre 1=gi_post 2=gi_dec
// ---------------------------------------------------------------------------
#define BK 16
__global__ __launch_bounds__(256, 3) void gemm_gather(
    const int* __restrict__ tokens_arg, int dst,
    const float* __restrict__ emb,
    const float* __restrict__ W,
    const float* __restrict__ bias)
{
    const int* tokens = (dst == 2) ? g_dtok : tokens_arg;
    float* C = (dst == 0) ? g_gi[0] : (dst == 1) ? g_gi[1] : g_gid;

    __shared__ __align__(16) float As[BK][64];    // [k][m]
    __shared__ __align__(16) float Bs[BK][128];   // [k][n]

    int tid = threadIdx.x;
    int m0 = blockIdx.x * 64;
    int n0 = blockIdx.y * 128;

    // A staging: 64 rows x 16 k; thread -> (m = tid&63, kg = tid>>6) 1 float4
    int am = tid & 63;
    int akg = (tid >> 6) << 2;          // 0,4,8,12
    int tokm = tokens[m0 + am];
    const float* arow = emb + (size_t)tokm * Dd + akg;

    // B staging: 128 rows x 16 k; thread -> (n = tid&127, kg2 = tid>>7) 2 float4
    int bn = tid & 127;
    int bkg = (tid >> 7) << 3;          // 0 or 8
    const float* brow = W + (size_t)(n0 + bn) * Dd + bkg;

    int tx = tid & 31;                  // n microtile (4 cols)
    int ty = tid >> 5;                  // m microtile (8 rows)

    float acc[8][4];
    #pragma unroll
    for (int i = 0; i < 8; i++)
        #pragma unroll
        for (int j = 0; j < 4; j++) acc[i][j] = 0.f;

    // prefetch first K-tile
    float4 pa  = *(const float4*)(arow);
    float4 pb0 = *(const float4*)(brow);
    float4 pb1 = *(const float4*)(brow + 4);

    for (int k0 = 0; k0 < Dd; k0 += BK) {
        __syncthreads();
        As[akg + 0][am] = pa.x; As[akg + 1][am] = pa.y;
        As[akg + 2][am] = pa.z; As[akg + 3][am] = pa.w;
        Bs[bkg + 0][bn] = pb0.x; Bs[bkg + 1][bn] = pb0.y;
        Bs[bkg + 2][bn] = pb0.z; Bs[bkg + 3][bn] = pb0.w;
        Bs[bkg + 4][bn] = pb1.x; Bs[bkg + 5][bn] = pb1.y;
        Bs[bkg + 6][bn] = pb1.z; Bs[bkg + 7][bn] = pb1.w;
        __syncthreads();
        if (k0 + BK < Dd) {             // prefetch next tile (overlaps compute)
            pa  = *(const float4*)(arow + k0 + BK);
            pb0 = *(const float4*)(brow + k0 + BK);
            pb1 = *(const float4*)(brow + k0 + BK + 4);
        }
        #pragma unroll
        for (int kk = 0; kk < BK; kk++) {
            float4 av0 = *(const float4*)&As[kk][ty * 8];      // warp-uniform
            float4 av1 = *(const float4*)&As[kk][ty * 8 + 4];  // warp-uniform
            float4 bv  = *(const float4*)&Bs[kk][tx * 4];
            float a[8] = {av0.x, av0.y, av0.z, av0.w, av1.x, av1.y, av1.z, av1.w};
            float b[4] = {bv.x, bv.y, bv.z, bv.w};
            #pragma unroll
            for (int i = 0; i < 8; i++)
                #pragma unroll
                for (int j = 0; j < 4; j++) acc[i][j] += a[i] * b[j];
        }
    }

    int n = n0 + tx * 4;
    float4 bo = *(const float4*)(bias + n);
    #pragma unroll
    for (int i = 0; i < 8; i++) {
        int m = m0 + ty * 8 + i;
        float4 o;
        o.x = acc[i][0] + bo.x;
        o.y = acc[i][1] + bo.y;
        o.z = acc[i][2] + bo.z;
        o.w = acc[i][3] + bo.w;
        *(float4*)&C[(size_t)m * G3 + n] = o;
    }
}

// ---------------------------------------------------------------------------
// GRU step (R4-exact, the measured-best recurrence).
// CTA owns 8 h-columns; Whh slice (24 rows x 512) staged in smem (48KB).
// 256 threads: jj = tid>>5 (0..7), bg = tid&31 -> 2 batches (bg*2, bg*2+1).
// h layout [j][b] (j-major), so h reads are coalesced.
// ---------------------------------------------------------------------------
#define FMA2(hv, wrv, wzv, wnv)                                               \
    accr[0] += hv.x * wrv; accr[1] += hv.y * wrv;                             \
    accz[0] += hv.x * wzv; accz[1] += hv.y * wzv;                             \
    accn[0] += hv.x * wnv; accn[1] += hv.y * wnv;

__device__ __forceinline__ float fsigmoid(float x) {
    return 1.f / (1.f + __expf(-x));
}

__global__ __launch_bounds__(256) void gru_step(
    int isDec, int t,
    const float* __restrict__ Whh0, const float* __restrict__ Whh1,
    const float* __restrict__ bhh0, const float* __restrict__ bhh1)
{
    int gru = blockIdx.y;
    const float* gi  = isDec ? g_gid : g_gi[gru];
    float* hist      = isDec ? g_dhist : g_hist[gru];
    const float* Whh = gru ? Whh1 : Whh0;
    const float* bhh = gru ? bhh1 : bhh0;
    int seq = isDec ? Tt : Ss;

    const float* h_in = hist + (size_t)t * HB;
    float* h_out      = hist + (size_t)(t + 1) * HB;

    __shared__ __align__(16) float sw[24 * 512];   // exactly 48KB
    int tid = threadIdx.x;
    int j0 = blockIdx.x * 8;
    {
        const float4* W4 = (const float4*)Whh;
        float4* sw4 = (float4*)sw;
        #pragma unroll
        for (int i = 0; i < 12; i++) {
            int idx = i * 256 + tid;          // 0..3071 float4s
            int r = idx >> 7, c = idx & 127;
            int gate = r >> 3, jj = r & 7;
            int row = gate * Hh + j0 + jj;
            sw4[idx] = W4[(size_t)row * 128 + c];
        }
    }
    __syncthreads();

    int jj = tid >> 5;    // 0..7
    int bg = tid & 31;    // 0..31 -> batch pair (2*bg, 2*bg+1)
    const float2* h2  = (const float2*)h_in;
    const float4* swr = (const float4*)(sw + jj * 512);
    const float4* swz = (const float4*)(sw + (8 + jj) * 512);
    const float4* swn = (const float4*)(sw + (16 + jj) * 512);

    float accr[2] = {0.f, 0.f};
    float accz[2] = {0.f, 0.f};
    float accn[2] = {0.f, 0.f};

    #pragma unroll 4
    for (int k4 = 0; k4 < 128; k4++) {
        float4 wr = swr[k4], wz = swz[k4], wn = swn[k4];
        float2 hA = h2[(k4 * 4 + 0) * 32 + bg];
        float2 hB = h2[(k4 * 4 + 1) * 32 + bg];
        float2 hC = h2[(k4 * 4 + 2) * 32 + bg];
        float2 hD = h2[(k4 * 4 + 3) * 32 + bg];
        FMA2(hA, wr.x, wz.x, wn.x)
        FMA2(hB, wr.y, wz.y, wn.y)
        FMA2(hC, wr.z, wz.z, wn.z)
        FMA2(hD, wr.w, wz.w, wn.w)
    }

    int j = j0 + jj;
    float br = bhh[j], bz = bhh[Hh + j], bn = bhh[2 * Hh + j];
    float2 hold = h2[j * 32 + bg];
    float holdv[2] = {hold.x, hold.y};
    float ho[2];
    #pragma unroll
    for (int i = 0; i < 2; i++) {
        int b = bg * 2 + i;
        const float* g = gi + ((size_t)b * seq + t) * G3;
        float r = fsigmoid(g[j]          + accr[i] + br);
        float z = fsigmoid(g[Hh + j]     + accz[i] + bz);
        float n = tanhf(g[2 * Hh + j] + r * (accn[i] + bn));
        ho[i] = (1.f - z) * n + z * holdv[i];
    }
    *(float2*)&h_out[j * Bb + bg * 2] = make_float2(ho[0], ho[1]);
}

// ---------------------------------------------------------------------------
// score_enc[b][gru*S + t] = sum_j relu(h_{t+1}[j][b]) * w_enc[j]
// ---------------------------------------------------------------------------
__global__ __launch_bounds__(64) void score_kernel(const float* __restrict__ out_w) {
    int t = blockIdx.x, gru = blockIdx.y, b = threadIdx.x;
    const float* hrow = g_hist[gru] + (size_t)(t + 1) * HB;
    float acc = 0.f;
    for (int j = 0; j < Hh; j++)
        acc += fmaxf(hrow[j * Bb + b], 0.f) * out_w[j];
    g_score[b * (2 * Ss) + gru * Ss + t] = acc;
}

// ---------------------------------------------------------------------------
// enc_hidden (decoder h0) = tanh(cat(pre_h, post_h) @ enc_fc_w^T + enc_fc_b)
// ---------------------------------------------------------------------------
__global__ __launch_bounds__(64) void ench_kernel(const float* __restrict__ enc_fc_w,
                                                  const float* __restrict__ enc_fc_b) {
    int i = blockIdx.x, b = threadIdx.x;
    const float* w = enc_fc_w + (size_t)i * (2 * Hh);
    const float* hp0 = g_hist[0] + (size_t)Ss * HB;
    const float* hp1 = g_hist[1] + (size_t)Ss * HB;
    float acc = enc_fc_b[i];
    for (int q = 0; q < Hh; q++) acc += hp0[q * Bb + b] * w[q];
    for (int q = 0; q < Hh; q++) acc += hp1[q * Bb + b] * w[Hh + q];
    g_dhist[i * Bb + b] = tanhf(acc);
}

// ---------------------------------------------------------------------------
// decoder hidden score: hsc[t][b] = relu(hdec_{t+1}[:,b]) . w_hid + out_b
// ---------------------------------------------------------------------------
__global__ __launch_bounds__(64) void hsc_kernel(const float* __restrict__ out_w,
                                                 const float* __restrict__ out_b) {
    int t = blockIdx.x, b = threadIdx.x;
    const float* hrow = g_dhist + (size_t)(t + 1) * HB;
    float acc = 0.f;
    for (int j = 0; j < Hh; j++)
        acc += fmaxf(hrow[j * Bb + b], 0.f) * out_w[Hh + j];
    g_hsc[t * Bb + b] = acc + out_b[0];
}

// ---------------------------------------------------------------------------
// probs: out_pre[b][t][s] = sigmoid(score[b][s] + hsc[t][b]); post analogous
// ---------------------------------------------------------------------------
__global__ __launch_bounds__(256) void probs_kernel(float* __restrict__ out) {
    int bt = blockIdx.x;             // 0..4095
    int b = bt >> 6, t = bt & 63;
    float hs = g_hsc[t * Bb + b];
    const float* sc = g_score + b * (2 * Ss);
    float* out_pre  = out + (size_t)bt * Ss;
    float* out_post = out + (size_t)Bb * Tt * Ss + (size_t)bt * Ss;
    #pragma unroll
    for (int it = 0; it < 4; it++) {
        int s2 = it * 256 + threadIdx.x;
        float l = sc[s2] + hs;
        float p = 1.f / (1.f + expf(-l));
        if (s2 < Ss) out_pre[s2] = p;
        else         out_post[s2 - Ss] = p;
    }
}

// ---------------------------------------------------------------------------
// launch
// ---------------------------------------------------------------------------
extern "C" void kernel_launch(void* const* d_in, const int* in_sizes, int n_in,
                              void* d_out, int out_size) {
    const int*   pre_seq   = (const int*)  d_in[0];
    const int*   post_seq  = (const int*)  d_in[1];
    const int*   trg       = (const int*)  d_in[2];
    const float* emb       = (const float*)d_in[3];
    const float* pre_Wih   = (const float*)d_in[4];
    const float* pre_Whh   = (const float*)d_in[5];
    const float* pre_bih   = (const float*)d_in[6];
    const float* pre_bhh   = (const float*)d_in[7];
    const float* post_Wih  = (const float*)d_in[8];
    const float* post_Whh  = (const float*)d_in[9];
    const float* post_bih  = (const float*)d_in[10];
    const float* post_bhh  = (const float*)d_in[11];
    const float* enc_fc_w  = (const float*)d_in[12];
    const float* enc_fc_b  = (const float*)d_in[13];
    const float* dec_Wih   = (const float*)d_in[14];
    const float* dec_Whh   = (const float*)d_in[15];
    const float* dec_bih   = (const float*)d_in[16];
    const float* dec_bhh   = (const float*)d_in[17];
    const float* out_w     = (const float*)d_in[18];
    const float* out_b     = (const float*)d_in[19];
    float* out = (float*)d_out;

    // h0 = 0 and decoder token assembly
    init_kernel<<<128, 256>>>();
    dectok_kernel<<<16, 256>>>(pre_seq, trg);

    // Gate-input GEMMs (fused embedding gather): gi = emb[tok] @ Wih^T + bih
    gemm_gather<<<dim3(Bb * Ss / 64, G3 / 128), 256>>>(pre_seq,  0, emb, pre_Wih,  pre_bih);
    gemm_gather<<<dim3(Bb * Ss / 64, G3 / 128), 256>>>(post_seq, 1, emb, post_Wih, post_bih);
    gemm_gather<<<dim3(Bb * Tt / 64, G3 / 128), 256>>>(nullptr,  2, emb, dec_Wih,  dec_bih);

    // Encoder recurrences (pre + post in one grid per step)
    for (int t = 0; t < Ss; t++)
        gru_step<<<dim3(Hh / 8, 2), 256>>>(0, t, pre_Whh, post_Whh, pre_bhh, post_bhh);

    // score_enc over all encoder outputs; decoder initial hidden
    score_kernel<<<dim3(Ss, 2), 64>>>(out_w);
    ench_kernel<<<Hh, 64>>>(enc_fc_w, enc_fc_b);

    // Decoder recurrence
    for (int t = 0; t < Tt; t++)
        gru_step<<<dim3(Hh / 8, 1), 256>>>(1, t, dec_Whh, dec_Whh, dec_bhh, dec_bhh);

    // Logits -> probabilities -> output
    hsc_kernel<<<Tt, 64>>>(out_w, out_b);
    probs_kernel<<<Bb * Tt, 256>>>(out);
}